// round 1
// baseline (speedup 1.0000x reference)
#include <cuda_runtime.h>

#define CM 256
#define CZ 128
#define NRES 768
#define SDIM 128
#define LN_EPS 1e-5f

// ---------------------------------------------------------------------------
// Kernel 1: out_m[0, n, :] = m[0, n, :] + LayerNorm(m_prev[0, n, :])
// One warp per row n (768 rows, C_M=256 channels -> 2 float4 per lane).
// ---------------------------------------------------------------------------
__global__ void m_ln_add_kernel(const float* __restrict__ m,
                                const float* __restrict__ m_prev,
                                const float* __restrict__ ln_w,
                                const float* __restrict__ ln_b,
                                float* __restrict__ out) {
    int warp = (blockIdx.x * blockDim.x + threadIdx.x) >> 5;
    int lane = threadIdx.x & 31;
    if (warp >= NRES) return;

    const float4* mp = reinterpret_cast<const float4*>(m_prev + (size_t)warp * CM);
    float4 a = mp[lane];
    float4 b = mp[lane + 32];

    float s  = a.x + a.y + a.z + a.w + b.x + b.y + b.z + b.w;
    float ss = a.x*a.x + a.y*a.y + a.z*a.z + a.w*a.w
             + b.x*b.x + b.y*b.y + b.z*b.z + b.w*b.w;
    #pragma unroll
    for (int o = 16; o; o >>= 1) {
        s  += __shfl_xor_sync(0xffffffffu, s,  o);
        ss += __shfl_xor_sync(0xffffffffu, ss, o);
    }
    float mu   = s * (1.0f / CM);
    float var  = ss * (1.0f / CM) - mu * mu;
    float rstd = rsqrtf(var + LN_EPS);

    const float4* mr = reinterpret_cast<const float4*>(m + (size_t)warp * CM);
    const float4* wv = reinterpret_cast<const float4*>(ln_w);
    const float4* bv = reinterpret_cast<const float4*>(ln_b);
    float4* ov = reinterpret_cast<float4*>(out + (size_t)warp * CM);

    {
        float4 mm = mr[lane];
        float4 w  = wv[lane];
        float4 bb = bv[lane];
        float4 o;
        o.x = mm.x + (a.x - mu) * rstd * w.x + bb.x;
        o.y = mm.y + (a.y - mu) * rstd * w.y + bb.y;
        o.z = mm.z + (a.z - mu) * rstd * w.z + bb.z;
        o.w = mm.w + (a.w - mu) * rstd * w.w + bb.w;
        ov[lane] = o;
    }
    {
        float4 mm = mr[lane + 32];
        float4 w  = wv[lane + 32];
        float4 bb = bv[lane + 32];
        float4 o;
        o.x = mm.x + (b.x - mu) * rstd * w.x + bb.x;
        o.y = mm.y + (b.y - mu) * rstd * w.y + bb.y;
        o.z = mm.z + (b.z - mu) * rstd * w.z + bb.z;
        o.w = mm.w + (b.w - mu) * rstd * w.w + bb.w;
        ov[lane + 32] = o;
    }
}

// ---------------------------------------------------------------------------
// Kernel 2: out_z[i,j,:] = z[i,j,:] + LayerNorm(z_prev[i,j,:]) + lin_w[:,bin] + lin_b
// One warp per (i,j) row (589824 rows, C_Z=128 -> 1 float4 per lane).
// ---------------------------------------------------------------------------
__global__ void z_kernel(const float* __restrict__ z,
                         const float* __restrict__ z_prev,
                         const float* __restrict__ x,
                         const float* __restrict__ ln_w,
                         const float* __restrict__ ln_b,
                         const float* __restrict__ lin_w,
                         const float* __restrict__ lin_b,
                         float* __restrict__ out) {
    // Transposed lin_w table in shared: lin_s[bin][c]; row 15 = zeros (no bin hit).
    __shared__ float lin_s[16 * CZ];
    for (int idx = threadIdx.x; idx < 15 * CZ; idx += blockDim.x) {
        int bb = idx >> 7;          // bin
        int c  = idx & (CZ - 1);    // channel
        lin_s[idx] = lin_w[c * 15 + bb];
    }
    for (int idx = threadIdx.x; idx < CZ; idx += blockDim.x)
        lin_s[15 * CZ + idx] = 0.0f;
    __syncthreads();

    int row = blockIdx.x * (blockDim.x >> 5) + (threadIdx.x >> 5);
    int lane = threadIdx.x & 31;
    if (row >= NRES * NRES) return;

    int i = row / NRES;
    int j = row - i * NRES;

    // pairwise distance (broadcast loads; all lanes compute redundantly)
    float dx = x[3 * i + 0] - x[3 * j + 0];
    float dy = x[3 * i + 1] - x[3 * j + 1];
    float dz = x[3 * i + 2] - x[3 * j + 2];
    float d = sqrtf(dx * dx + dy * dy + dz * dz);

    int bin = 15;  // "no bin" row (zeros)
    #pragma unroll
    for (int k = 0; k < 15; k++) {
        float lo = 3.25f + 1.25f * (float)k;   // exact quarter values, == linspace
        float hi = (k < 14) ? (lo + 1.25f) : 1e8f;
        if (d > lo && d < hi) bin = k;
    }

    const float4* zp = reinterpret_cast<const float4*>(z_prev + (size_t)row * CZ);
    float4 v = zp[lane];
    float s  = v.x + v.y + v.z + v.w;
    float ss = v.x*v.x + v.y*v.y + v.z*v.z + v.w*v.w;
    #pragma unroll
    for (int o = 16; o; o >>= 1) {
        s  += __shfl_xor_sync(0xffffffffu, s,  o);
        ss += __shfl_xor_sync(0xffffffffu, ss, o);
    }
    float mu   = s * (1.0f / CZ);
    float var  = ss * (1.0f / CZ) - mu * mu;
    float rstd = rsqrtf(var + LN_EPS);

    float4 zr = reinterpret_cast<const float4*>(z + (size_t)row * CZ)[lane];
    float4 w  = reinterpret_cast<const float4*>(ln_w)[lane];
    float4 bb = reinterpret_cast<const float4*>(ln_b)[lane];
    float4 lb = reinterpret_cast<const float4*>(lin_b)[lane];
    float4 lw = *reinterpret_cast<const float4*>(&lin_s[bin * CZ + lane * 4]);

    float4 o;
    o.x = zr.x + lw.x + lb.x + (v.x - mu) * rstd * w.x + bb.x;
    o.y = zr.y + lw.y + lb.y + (v.y - mu) * rstd * w.y + bb.y;
    o.z = zr.z + lw.z + lb.z + (v.z - mu) * rstd * w.z + bb.z;
    o.w = zr.w + lw.w + lb.w + (v.w - mu) * rstd * w.w + bb.w;
    reinterpret_cast<float4*>(out + (size_t)row * CZ)[lane] = o;
}

extern "C" void kernel_launch(void* const* d_in, const int* in_sizes, int n_in,
                              void* d_out, int out_size) {
    const float* m      = (const float*)d_in[0];
    const float* z      = (const float*)d_in[1];
    const float* m_prev = (const float*)d_in[2];
    const float* z_prev = (const float*)d_in[3];
    const float* x_prev = (const float*)d_in[4];
    const float* ln_m_w = (const float*)d_in[5];
    const float* ln_m_b = (const float*)d_in[6];
    const float* ln_z_w = (const float*)d_in[7];
    const float* ln_z_b = (const float*)d_in[8];
    const float* lin_w  = (const float*)d_in[9];
    const float* lin_b  = (const float*)d_in[10];

    float* out = (float*)d_out;
    const size_t m_elems = (size_t)SDIM * NRES * CM;   // 25,165,824
    float* out_z = out + m_elems;

    // 1) bulk copy of m -> out_m (the [1:,...] slices are unchanged)
    cudaMemcpyAsync(out, m, m_elems * sizeof(float), cudaMemcpyDeviceToDevice, 0);

    // 2) overwrite out_m[0,:,:] with m[0,:,:] + LN(m_prev[0,:,:])
    //    768 rows, 1 warp each, 8 warps/block -> 96 blocks
    m_ln_add_kernel<<<96, 256>>>(m, m_prev, ln_m_w, ln_m_b, out);

    // 3) z path: 589824 rows, 1 warp each, 8 warps/block -> 73728 blocks
    z_kernel<<<(NRES * NRES) / 8, 256>>>(z, z_prev, x_prev,
                                         ln_z_w, ln_z_b, lin_w, lin_b, out_z);
}

// round 2
// speedup vs baseline: 1.3229x; 1.3229x over previous
#include <cuda_runtime.h>

#define CM 256
#define CZ 128
#define NRES 768
#define SDIM 128
#define LN_EPS 1e-5f

// Block-role layout (all in one fused kernel, 256 threads/block):
//   [0, NZ_BLOCKS)                     : z path, 16 rows/block (2 rows/warp)
//   [NZ_BLOCKS, NZ_BLOCKS+NM_BLOCKS)   : m row-0 LN-add, 8 rows/block
//   [.., +NCOPY_BLOCKS)                : bulk m copy (skipping the 768*256 floats of slice 0)
#define NZ_BLOCKS    36864   // 589824 rows / 16
#define NM_BLOCKS    96      // 768 rows / 8
#define NCOPY_BLOCKS 6096    // (25165824 - 196608) floats / 4 / 1024
#define M_ELEMS      25165824          // SDIM*NRES*CM
#define M_SKIP4      49152             // 768*256/4  (slice-0 float4s, handled by LN blocks)

__global__ void __launch_bounds__(256) fused_kernel(
        const float* __restrict__ m,
        const float* __restrict__ z,
        const float* __restrict__ m_prev,
        const float* __restrict__ z_prev,
        const float* __restrict__ x,
        const float* __restrict__ ln_m_w,
        const float* __restrict__ ln_m_b,
        const float* __restrict__ ln_z_w,
        const float* __restrict__ ln_z_b,
        const float* __restrict__ lin_w,
        const float* __restrict__ lin_b,
        float* __restrict__ out) {

    float* out_z = out + M_ELEMS;
    const unsigned bid = blockIdx.x;

    if (bid < NZ_BLOCKS) {
        // ------------------------------------------------------------------
        // z path: out_z[row,:] = z[row,:] + LN(z_prev[row,:]) + lin_w[:,bin] + lin_b
        // 2 rows per warp: half-warp (16 lanes) per row, 8 floats per lane.
        // ------------------------------------------------------------------
        // Combined table: tab[k][c] = lin_w[c*15+k] + lin_b[c] + ln_z_b[c], k<15
        //                 tab[15][c] = lin_b[c] + ln_z_b[c]   (no-bin row)
        __shared__ float tab[16 * CZ];
        for (int idx = threadIdx.x; idx < 16 * CZ; idx += 256) {
            int k = idx >> 7;
            int c = idx & (CZ - 1);
            float v = lin_b[c] + ln_z_b[c];
            if (k < 15) v += lin_w[c * 15 + k];
            tab[idx] = v;
        }
        __syncthreads();

        int wid  = threadIdx.x >> 5;
        int lane = threadIdx.x & 31;
        int h    = lane & 15;        // position within half-warp
        int row  = bid * 16 + wid * 2 + (lane >> 4);

        int i = row / NRES;          // constant divisor -> mul/shift
        int j = row - i * NRES;

        // distance -> bin (arithmetic, with strict-boundary recheck to match
        // the reference's exclusive (d>lo & d<hi) semantics)
        float dx = x[3 * i + 0] - x[3 * j + 0];
        float dy = x[3 * i + 1] - x[3 * j + 1];
        float dz = x[3 * i + 2] - x[3 * j + 2];
        float d  = sqrtf(fmaf(dx, dx, fmaf(dy, dy, dz * dz)));

        int bin = 15;                                   // default: no bin
        int k = (int)floorf((d - 3.25f) * 0.8f);        // /1.25
        if (k > 14) k = 14;
        if (k >= 0) {
            float lo = fmaf(1.25f, (float)k, 3.25f);
            float hi = (k == 14) ? 1e8f : (lo + 1.25f);
            if (d > lo && d < hi) bin = k;
            else if (k > 0 && d > lo - 1.25f && d < lo) bin = k - 1; // 1-ulp floor overshoot
        }

        const float4* zp = reinterpret_cast<const float4*>(z_prev + (size_t)row * CZ);
        float4 v0 = zp[h];
        float4 v1 = zp[h + 16];

        float s  = v0.x + v0.y + v0.z + v0.w + v1.x + v1.y + v1.z + v1.w;
        float ss = v0.x*v0.x + v0.y*v0.y + v0.z*v0.z + v0.w*v0.w
                 + v1.x*v1.x + v1.y*v1.y + v1.z*v1.z + v1.w*v1.w;
        #pragma unroll
        for (int o = 8; o; o >>= 1) {                    // stays within half-warp
            s  += __shfl_xor_sync(0xffffffffu, s,  o);
            ss += __shfl_xor_sync(0xffffffffu, ss, o);
        }
        float mu   = s * (1.0f / CZ);
        float var  = ss * (1.0f / CZ) - mu * mu;
        float rstd = rsqrtf(var + LN_EPS);

        const float4* zr = reinterpret_cast<const float4*>(z + (size_t)row * CZ);
        const float4* wv = reinterpret_cast<const float4*>(ln_z_w);
        const float4* tv = reinterpret_cast<const float4*>(&tab[bin * CZ]);
        float4* ov = reinterpret_cast<float4*>(out_z + (size_t)row * CZ);

        {
            float4 a = zr[h], w = wv[h], t = tv[h];
            float4 o;
            o.x = a.x + t.x + (v0.x - mu) * rstd * w.x;
            o.y = a.y + t.y + (v0.y - mu) * rstd * w.y;
            o.z = a.z + t.z + (v0.z - mu) * rstd * w.z;
            o.w = a.w + t.w + (v0.w - mu) * rstd * w.w;
            ov[h] = o;
        }
        {
            float4 a = zr[h + 16], w = wv[h + 16], t = tv[h + 16];
            float4 o;
            o.x = a.x + t.x + (v1.x - mu) * rstd * w.x;
            o.y = a.y + t.y + (v1.y - mu) * rstd * w.y;
            o.z = a.z + t.z + (v1.z - mu) * rstd * w.z;
            o.w = a.w + t.w + (v1.w - mu) * rstd * w.w;
            ov[h + 16] = o;
        }
    } else if (bid < NZ_BLOCKS + NM_BLOCKS) {
        // ------------------------------------------------------------------
        // m slice 0: out[0,n,:] = m[0,n,:] + LN(m_prev[0,n,:])
        // 1 warp per row, 8 floats per lane (2 float4).
        // ------------------------------------------------------------------
        int mb   = bid - NZ_BLOCKS;
        int wid  = threadIdx.x >> 5;
        int lane = threadIdx.x & 31;
        int row  = mb * 8 + wid;     // < 768

        const float4* mp = reinterpret_cast<const float4*>(m_prev + (size_t)row * CM);
        float4 a = mp[lane];
        float4 b = mp[lane + 32];

        float s  = a.x + a.y + a.z + a.w + b.x + b.y + b.z + b.w;
        float ss = a.x*a.x + a.y*a.y + a.z*a.z + a.w*a.w
                 + b.x*b.x + b.y*b.y + b.z*b.z + b.w*b.w;
        #pragma unroll
        for (int o = 16; o; o >>= 1) {
            s  += __shfl_xor_sync(0xffffffffu, s,  o);
            ss += __shfl_xor_sync(0xffffffffu, ss, o);
        }
        float mu   = s * (1.0f / CM);
        float var  = ss * (1.0f / CM) - mu * mu;
        float rstd = rsqrtf(var + LN_EPS);

        const float4* mr = reinterpret_cast<const float4*>(m + (size_t)row * CM);
        const float4* wv = reinterpret_cast<const float4*>(ln_m_w);
        const float4* bv = reinterpret_cast<const float4*>(ln_m_b);
        float4* ov = reinterpret_cast<float4*>(out + (size_t)row * CM);

        {
            float4 mm = mr[lane], w = wv[lane], bb = bv[lane];
            float4 o;
            o.x = mm.x + (a.x - mu) * rstd * w.x + bb.x;
            o.y = mm.y + (a.y - mu) * rstd * w.y + bb.y;
            o.z = mm.z + (a.z - mu) * rstd * w.z + bb.z;
            o.w = mm.w + (a.w - mu) * rstd * w.w + bb.w;
            ov[lane] = o;
        }
        {
            float4 mm = mr[lane + 32], w = wv[lane + 32], bb = bv[lane + 32];
            float4 o;
            o.x = mm.x + (b.x - mu) * rstd * w.x + bb.x;
            o.y = mm.y + (b.y - mu) * rstd * w.y + bb.y;
            o.z = mm.z + (b.z - mu) * rstd * w.z + bb.z;
            o.w = mm.w + (b.w - mu) * rstd * w.w + bb.w;
            ov[lane + 32] = o;
        }
    } else {
        // ------------------------------------------------------------------
        // bulk copy of m[1:,...] -> out (slice 0 is written by LN blocks)
        // 1024 float4 per block (256 threads x 4).
        // ------------------------------------------------------------------
        unsigned cb = bid - (NZ_BLOCKS + NM_BLOCKS);
        const float4* src = reinterpret_cast<const float4*>(m);
        float4* dst = reinterpret_cast<float4*>(out);
        size_t base = (size_t)M_SKIP4 + (size_t)cb * 1024 + threadIdx.x;
        #pragma unroll
        for (int k = 0; k < 4; k++)
            dst[base + k * 256] = src[base + k * 256];
    }
}

extern "C" void kernel_launch(void* const* d_in, const int* in_sizes, int n_in,
                              void* d_out, int out_size) {
    const float* m      = (const float*)d_in[0];
    const float* z      = (const float*)d_in[1];
    const float* m_prev = (const float*)d_in[2];
    const float* z_prev = (const float*)d_in[3];
    const float* x_prev = (const float*)d_in[4];
    const float* ln_m_w = (const float*)d_in[5];
    const float* ln_m_b = (const float*)d_in[6];
    const float* ln_z_w = (const float*)d_in[7];
    const float* ln_z_b = (const float*)d_in[8];
    const float* lin_w  = (const float*)d_in[9];
    const float* lin_b  = (const float*)d_in[10];

    fused_kernel<<<NZ_BLOCKS + NM_BLOCKS + NCOPY_BLOCKS, 256>>>(
        m, z, m_prev, z_prev, x_prev,
        ln_m_w, ln_m_b, ln_z_w, ln_z_b, lin_w, lin_b, (float*)d_out);
}

// round 4
// speedup vs baseline: 1.4753x; 1.1152x over previous
#include <cuda_runtime.h>

#define CM 256
#define CZ 128
#define NRES 768
#define SDIM 128
#define LN_EPS 1e-5f

// Block-role layout (fused kernel, 256 threads/block):
//   [0, NZ_BLOCKS)                     : z path, 16 rows/block (2 rows/warp)
//   [NZ_BLOCKS, NZ_BLOCKS+NM_BLOCKS)   : m row-0 LN-add, 8 rows/block
//   [.., +NCOPY_BLOCKS)                : bulk m copy (skipping slice 0)
#define NZ_BLOCKS    36864   // 589824 / 16
#define NM_BLOCKS    96      // 768 / 8
#define NCOPY_BLOCKS 6096    // (25165824 - 196608)/4/1024
#define M_ELEMS      25165824
#define M_SKIP4      49152   // 768*256/4

// Precomputed table: tab_g[k][c] = lin_w[c*15+k] + lin_b[c] + ln_z_b[c] (k<15),
//                    tab_g[15][c] = lin_b[c] + ln_z_b[c]  ("no bin")
__device__ float tab_g[16 * CZ];

__global__ void setup_kernel(const float* __restrict__ lin_w,
                             const float* __restrict__ lin_b,
                             const float* __restrict__ ln_z_b) {
    int k = blockIdx.x;        // 0..15
    int c = threadIdx.x;       // 0..127
    float v = lin_b[c] + ln_z_b[c];
    if (k < 15) v += lin_w[c * 15 + k];
    tab_g[k * CZ + c] = v;
}

__global__ void __launch_bounds__(256) fused_kernel(
        const float* __restrict__ m,
        const float* __restrict__ z,
        const float* __restrict__ m_prev,
        const float* __restrict__ z_prev,
        const float* __restrict__ x,
        const float* __restrict__ ln_m_w,
        const float* __restrict__ ln_m_b,
        const float* __restrict__ ln_z_w,
        float* __restrict__ out) {

    float* out_z = out + M_ELEMS;
    const unsigned bid = blockIdx.x;

    if (bid < NZ_BLOCKS) {
        // ------------------------------------------------------------------
        // z path: out_z[row,:] = z[row,:] + LN(z_prev[row,:]) + tab[bin,:]
        // 2 rows per warp: half-warp per row, 8 floats per lane.
        // ------------------------------------------------------------------
        int wid  = threadIdx.x >> 5;
        int lane = threadIdx.x & 31;
        int h    = lane & 15;
        int row  = bid * 16 + wid * 2 + (lane >> 4);

        int i = row / NRES;
        int j = row - i * NRES;

        float dx = x[3 * i + 0] - x[3 * j + 0];
        float dy = x[3 * i + 1] - x[3 * j + 1];
        float dz = x[3 * i + 2] - x[3 * j + 2];
        float d  = sqrtf(fmaf(dx, dx, fmaf(dy, dy, dz * dz)));

        // Robust bin:
        //  - clamp k0 to 15 so d >> 20.75 still tests the open-ended bin 14
        //    (candidates {14,15,16})
        //  - +/-1 candidate loop absorbs floor() rounding either direction
        //  - edges 3.25+1.25k are fp32-exact, so the exact (d>lo && d<hi)
        //    test matches the reference bit-for-bit
        int bin = 15;
        int k0 = (int)floorf((d - 3.25f) * 0.8f);
        if (k0 > 15) k0 = 15;
        #pragma unroll
        for (int dk = -1; dk <= 1; dk++) {
            int k = k0 + dk;
            if (k >= 0 && k <= 14) {
                float lo = fmaf(1.25f, (float)k, 3.25f);
                float hi = (k == 14) ? 1e8f : (lo + 1.25f);
                if (d > lo && d < hi) bin = k;
            }
        }

        const float4* zp = reinterpret_cast<const float4*>(z_prev + (size_t)row * CZ);
        float4 v0 = __ldcs(zp + h);
        float4 v1 = __ldcs(zp + h + 16);

        float s  = v0.x + v0.y + v0.z + v0.w + v1.x + v1.y + v1.z + v1.w;
        float ss = v0.x*v0.x + v0.y*v0.y + v0.z*v0.z + v0.w*v0.w
                 + v1.x*v1.x + v1.y*v1.y + v1.z*v1.z + v1.w*v1.w;
        #pragma unroll
        for (int o = 8; o; o >>= 1) {
            s  += __shfl_xor_sync(0xffffffffu, s,  o);
            ss += __shfl_xor_sync(0xffffffffu, ss, o);
        }
        float mu   = s * (1.0f / CZ);
        float var  = ss * (1.0f / CZ) - mu * mu;
        float rstd = rsqrtf(var + LN_EPS);

        const float4* zr = reinterpret_cast<const float4*>(z + (size_t)row * CZ);
        const float4* wv = reinterpret_cast<const float4*>(ln_z_w);
        const float4* tv = reinterpret_cast<const float4*>(&tab_g[bin * CZ]);
        float4* ov = reinterpret_cast<float4*>(out_z + (size_t)row * CZ);

        {
            float4 a = __ldcs(zr + h);
            float4 w = wv[h], t = tv[h];
            float4 o;
            o.x = a.x + t.x + (v0.x - mu) * rstd * w.x;
            o.y = a.y + t.y + (v0.y - mu) * rstd * w.y;
            o.z = a.z + t.z + (v0.z - mu) * rstd * w.z;
            o.w = a.w + t.w + (v0.w - mu) * rstd * w.w;
            __stcs(ov + h, o);
        }
        {
            float4 a = __ldcs(zr + h + 16);
            float4 w = wv[h + 16], t = tv[h + 16];
            float4 o;
            o.x = a.x + t.x + (v1.x - mu) * rstd * w.x;
            o.y = a.y + t.y + (v1.y - mu) * rstd * w.y;
            o.z = a.z + t.z + (v1.z - mu) * rstd * w.z;
            o.w = a.w + t.w + (v1.w - mu) * rstd * w.w;
            __stcs(ov + h + 16, o);
        }
    } else if (bid < NZ_BLOCKS + NM_BLOCKS) {
        // ------------------------------------------------------------------
        // m slice 0: out[0,n,:] = m[0,n,:] + LN(m_prev[0,n,:])
        // ------------------------------------------------------------------
        int mb   = bid - NZ_BLOCKS;
        int wid  = threadIdx.x >> 5;
        int lane = threadIdx.x & 31;
        int row  = mb * 8 + wid;

        const float4* mp = reinterpret_cast<const float4*>(m_prev + (size_t)row * CM);
        float4 a = mp[lane];
        float4 b = mp[lane + 32];

        float s  = a.x + a.y + a.z + a.w + b.x + b.y + b.z + b.w;
        float ss = a.x*a.x + a.y*a.y + a.z*a.z + a.w*a.w
                 + b.x*b.x + b.y*b.y + b.z*b.z + b.w*b.w;
        #pragma unroll
        for (int o = 16; o; o >>= 1) {
            s  += __shfl_xor_sync(0xffffffffu, s,  o);
            ss += __shfl_xor_sync(0xffffffffu, ss, o);
        }
        float mu   = s * (1.0f / CM);
        float var  = ss * (1.0f / CM) - mu * mu;
        float rstd = rsqrtf(var + LN_EPS);

        const float4* mr = reinterpret_cast<const float4*>(m + (size_t)row * CM);
        const float4* wv = reinterpret_cast<const float4*>(ln_m_w);
        const float4* bv = reinterpret_cast<const float4*>(ln_m_b);
        float4* ov = reinterpret_cast<float4*>(out + (size_t)row * CM);

        {
            float4 mm = mr[lane], w = wv[lane], bb = bv[lane];
            float4 o;
            o.x = mm.x + (a.x - mu) * rstd * w.x + bb.x;
            o.y = mm.y + (a.y - mu) * rstd * w.y + bb.y;
            o.z = mm.z + (a.z - mu) * rstd * w.z + bb.z;
            o.w = mm.w + (a.w - mu) * rstd * w.w + bb.w;
            ov[lane] = o;
        }
        {
            float4 mm = mr[lane + 32], w = wv[lane + 32], bb = bv[lane + 32];
            float4 o;
            o.x = mm.x + (b.x - mu) * rstd * w.x + bb.x;
            o.y = mm.y + (b.y - mu) * rstd * w.y + bb.y;
            o.z = mm.z + (b.z - mu) * rstd * w.z + bb.z;
            o.w = mm.w + (b.w - mu) * rstd * w.w + bb.w;
            ov[lane + 32] = o;
        }
    } else {
        // ------------------------------------------------------------------
        // bulk copy of m[1:,...] -> out
        // ------------------------------------------------------------------
        unsigned cb = bid - (NZ_BLOCKS + NM_BLOCKS);
        const float4* src = reinterpret_cast<const float4*>(m);
        float4* dst = reinterpret_cast<float4*>(out);
        size_t base = (size_t)M_SKIP4 + (size_t)cb * 1024 + threadIdx.x;
        #pragma unroll
        for (int k = 0; k < 4; k++)
            __stcs(dst + base + k * 256, __ldcs(src + base + k * 256));
    }
}

extern "C" void kernel_launch(void* const* d_in, const int* in_sizes, int n_in,
                              void* d_out, int out_size) {
    const float* m      = (const float*)d_in[0];
    const float* z      = (const float*)d_in[1];
    const float* m_prev = (const float*)d_in[2];
    const float* z_prev = (const float*)d_in[3];
    const float* x_prev = (const float*)d_in[4];
    const float* ln_m_w = (const float*)d_in[5];
    const float* ln_m_b = (const float*)d_in[6];
    const float* ln_z_w = (const float*)d_in[7];
    const float* ln_z_b = (const float*)d_in[8];
    const float* lin_w  = (const float*)d_in[9];
    const float* lin_b  = (const float*)d_in[10];

    setup_kernel<<<16, 128>>>(lin_w, lin_b, ln_z_b);
    fused_kernel<<<NZ_BLOCKS + NM_BLOCKS + NCOPY_BLOCKS, 256>>>(
        m, z, m_prev, z_prev, x_prev,
        ln_m_w, ln_m_b, ln_z_w, (float*)d_out);
}